// round 3
// baseline (speedup 1.0000x reference)
#include <cuda_runtime.h>
#include <math.h>

#define B_   2
#define T_   2048
#define D_   2048
#define H_   16
#define HD_  128
#define LAT_ 512
#define RD_  64
#define CD_  64
#define M_   (B_*T_)   // 4096 rows total

// ------------------------------------------------------------------
// Scratch (device globals: the sanctioned alloc-free workaround)
// ------------------------------------------------------------------
__device__ float g_Q [M_*D_];        // (B,T,H,HD) flattened rows x 2048
__device__ float g_KV[M_*2*LAT_];    // rows x 1024 : [k_lat | v_lat]
__device__ float g_KR[M_*RD_];       // rows x 64   : roped shared key
__device__ float g_KC[M_*H_*CD_];    // rows x 1024 : per-head content key
__device__ float g_V [M_*D_];        // rows x 2048
__device__ float g_O [M_*D_];        // attention output rows x 2048

// ------------------------------------------------------------------
// fp32 GEMM:  C[M,N] = A[M,K](lda) * W[N,K](ldb)^T + bias[N]
// 128x128 tile, BK=16, 256 threads, 8x8 per thread.
// Register-prefetch + double-buffered smem: one sync per K-step.
// ------------------------------------------------------------------
__global__ __launch_bounds__(256) void sgemm_nt_bias(
    const float* __restrict__ A, int lda,
    const float* __restrict__ W, int ldb,
    const float* __restrict__ bias,
    float* __restrict__ C, int ldc,
    int Mdim, int Ndim, int Kdim)
{
    __shared__ float As[2][16][132];  // [buf][k][m]
    __shared__ float Bs[2][16][132];  // [buf][k][n]

    const int bm  = blockIdx.y * 128;
    const int bn  = blockIdx.x * 128;
    const int tid = threadIdx.x;
    const int tx  = tid & 15;      // n sub-tile
    const int ty  = tid >> 4;      // m sub-tile
    const int lr  = tid >> 2;      // load row 0..63
    const int lc  = (tid & 3) << 2;// load col 0,4,8,12

    float acc[8][8];
    #pragma unroll
    for (int i = 0; i < 8; i++)
        #pragma unroll
        for (int j = 0; j < 8; j++) acc[i][j] = 0.f;

    float4 pa[2], pb[2];           // prefetch registers

    // ---- prologue: fetch k0 = 0 ----
    #pragma unroll
    for (int half = 0; half < 2; half++) {
        const int row = lr + half * 64;
        const int m = bm + row;
        pa[half] = make_float4(0.f, 0.f, 0.f, 0.f);
        if (m < Mdim) pa[half] = *(const float4*)(A + (long)m * lda + lc);
        const int n = bn + row;
        pb[half] = make_float4(0.f, 0.f, 0.f, 0.f);
        if (n < Ndim) pb[half] = *(const float4*)(W + (long)n * ldb + lc);
    }
    #pragma unroll
    for (int half = 0; half < 2; half++) {
        const int row = lr + half * 64;
        As[0][lc+0][row] = pa[half].x; As[0][lc+1][row] = pa[half].y;
        As[0][lc+2][row] = pa[half].z; As[0][lc+3][row] = pa[half].w;
        Bs[0][lc+0][row] = pb[half].x; Bs[0][lc+1][row] = pb[half].y;
        Bs[0][lc+2][row] = pb[half].z; Bs[0][lc+3][row] = pb[half].w;
    }
    __syncthreads();

    int buf = 0;
    for (int k0 = 16; k0 < Kdim; k0 += 16) {
        // ---- issue global loads for next tile ----
        #pragma unroll
        for (int half = 0; half < 2; half++) {
            const int row = lr + half * 64;
            const int m = bm + row;
            pa[half] = make_float4(0.f, 0.f, 0.f, 0.f);
            if (m < Mdim) pa[half] = *(const float4*)(A + (long)m * lda + k0 + lc);
            const int n = bn + row;
            pb[half] = make_float4(0.f, 0.f, 0.f, 0.f);
            if (n < Ndim) pb[half] = *(const float4*)(W + (long)n * ldb + k0 + lc);
        }

        // ---- compute on current buffer (overlaps the loads above) ----
        #pragma unroll
        for (int kk = 0; kk < 16; kk++) {
            float a[8], bb[8];
            *(float4*)&a[0]  = *(const float4*)&As[buf][kk][ty*8];
            *(float4*)&a[4]  = *(const float4*)&As[buf][kk][ty*8+4];
            *(float4*)&bb[0] = *(const float4*)&Bs[buf][kk][tx*8];
            *(float4*)&bb[4] = *(const float4*)&Bs[buf][kk][tx*8+4];
            #pragma unroll
            for (int i = 0; i < 8; i++)
                #pragma unroll
                for (int j = 0; j < 8; j++)
                    acc[i][j] = fmaf(a[i], bb[j], acc[i][j]);
        }

        // ---- store prefetched tile into the other buffer ----
        const int nb = buf ^ 1;
        #pragma unroll
        for (int half = 0; half < 2; half++) {
            const int row = lr + half * 64;
            As[nb][lc+0][row] = pa[half].x; As[nb][lc+1][row] = pa[half].y;
            As[nb][lc+2][row] = pa[half].z; As[nb][lc+3][row] = pa[half].w;
            Bs[nb][lc+0][row] = pb[half].x; Bs[nb][lc+1][row] = pb[half].y;
            Bs[nb][lc+2][row] = pb[half].z; Bs[nb][lc+3][row] = pb[half].w;
        }
        __syncthreads();
        buf = nb;
    }

    // ---- epilogue compute on final buffer ----
    #pragma unroll
    for (int kk = 0; kk < 16; kk++) {
        float a[8], bb[8];
        *(float4*)&a[0]  = *(const float4*)&As[buf][kk][ty*8];
        *(float4*)&a[4]  = *(const float4*)&As[buf][kk][ty*8+4];
        *(float4*)&bb[0] = *(const float4*)&Bs[buf][kk][tx*8];
        *(float4*)&bb[4] = *(const float4*)&Bs[buf][kk][tx*8+4];
        #pragma unroll
        for (int i = 0; i < 8; i++)
            #pragma unroll
            for (int j = 0; j < 8; j++)
                acc[i][j] = fmaf(a[i], bb[j], acc[i][j]);
    }

    #pragma unroll
    for (int i = 0; i < 8; i++) {
        const int m = bm + ty*8 + i;
        if (m >= Mdim) continue;
        #pragma unroll
        for (int j = 0; j < 8; j++) {
            const int n = bn + tx*8 + j;
            if (n < Ndim) C[(long)m * ldc + n] = acc[i][j] + bias[n];
        }
    }
}

// ------------------------------------------------------------------
// RoPE (rotate-half). inv_freq = 10000^(-2j/64); pos = row % T.
// ------------------------------------------------------------------
__device__ __forceinline__ void rope_pair(int pos, int j, float& x1, float& x2)
{
    const float LOG2_THETA = 13.287712379549449f;   // log2(10000)
    float e   = (float)(2 * j) * (1.0f / (float)RD_);
    float inv = exp2f(-e * LOG2_THETA);
    float ang = (float)pos * inv;
    float s, c;
    sincosf(ang, &s, &c);
    float a = x1, b = x2;
    x1 = a * c - b * s;
    x2 = b * c + a * s;
}

__global__ void rope_kr_kernel()
{
    int r = blockIdx.x;       // 0..4095
    int j = threadIdx.x;      // 0..31
    int pos = r & (T_ - 1);
    float* p = g_KR + (long)r * RD_;
    float x1 = p[j], x2 = p[j + 32];
    rope_pair(pos, j, x1, x2);
    p[j] = x1; p[j + 32] = x2;
}

__global__ void rope_q_kernel()
{
    int r   = blockIdx.x;          // 0..4095
    int tid = threadIdx.x;         // 0..511
    int h = tid >> 5, j = tid & 31;
    int pos = r & (T_ - 1);
    float* p = g_Q + (long)r * D_ + h * HD_ + CD_;
    float x1 = p[j], x2 = p[j + 32];
    rope_pair(pos, j, x1, x2);
    p[j] = x1; p[j + 32] = x2;
}

// ------------------------------------------------------------------
// fp32 causal flash attention.  One CTA = (b,h) pair x 64-query tile.
// K assembled on the fly from g_KC (content, d<64) and g_KR (rope).
// ------------------------------------------------------------------
#define FL_SMEM_FLOATS (2*128*68 + 64*128 + 64*65 + 3*64)
#define FL_SMEM_BYTES  (FL_SMEM_FLOATS * 4)

__global__ __launch_bounds__(256) void flash_kernel()
{
    extern __shared__ float sm[];
    float* sQt = sm;                   // [128][68]  (d-major, transposed)
    float* sKt = sQt + 128*68;         // [128][68]
    float* sV  = sKt + 128*68;         // [64][128]
    float* sP  = sV  + 64*128;         // [64][65]   scores then probs
    float* sM  = sP  + 64*65;          // [64]
    float* sL  = sM  + 64;             // [64]
    float* sSc = sL  + 64;             // [64]

    const int qt = 31 - blockIdx.x;    // big tiles scheduled first
    const int pr = blockIdx.y;         // 0..31  (b,h)
    const int b  = pr >> 4, h = pr & 15;
    const int tid = threadIdx.x;
    const int tx = tid & 15, ty = tid >> 4;
    const int q0 = qt * 64;
    const int rowbase = b * T_;

    #pragma unroll 8
    for (int idx = tid; idx < 64*128; idx += 256) {
        int qi = idx >> 7, d = idx & 127;
        sQt[d*68 + qi] = g_Q[(long)(rowbase + q0 + qi) * D_ + h*HD_ + d];
    }
    if (tid < 64) { sM[tid] = -INFINITY; sL[tid] = 0.f; }

    float accO[4][8];
    #pragma unroll
    for (int i = 0; i < 4; i++)
        #pragma unroll
        for (int j = 0; j < 8; j++) accO[i][j] = 0.f;

    const float sc_qk = 0.08838834764831845f;   // 1/sqrt(128)

    for (int kb = 0; kb <= qt; kb++) {
        const int k0 = kb * 64;
        __syncthreads();    // previous consumers done before overwrite
        #pragma unroll 8
        for (int idx = tid; idx < 64*128; idx += 256) {
            int ki = idx >> 7, d = idx & 127;
            int r  = rowbase + k0 + ki;
            float kv = (d < CD_) ? g_KC[(long)r * (H_*CD_) + h*CD_ + d]
                                 : g_KR[(long)r * RD_ + (d - CD_)];
            sKt[d*68 + ki]  = kv;
            sV [ki*128 + d] = g_V[(long)r * D_ + h*HD_ + d];
        }
        __syncthreads();

        // ---- S = Q K^T  (4x4 per thread over 128 dims) ----
        float s00=0,s01=0,s02=0,s03=0, s10=0,s11=0,s12=0,s13=0;
        float s20=0,s21=0,s22=0,s23=0, s30=0,s31=0,s32=0,s33=0;
        #pragma unroll 4
        for (int d = 0; d < 128; d++) {
            float4 a = *(const float4*)&sQt[d*68 + ty*4];
            float4 k = *(const float4*)&sKt[d*68 + tx*4];
            s00 = fmaf(a.x, k.x, s00); s01 = fmaf(a.x, k.y, s01);
            s02 = fmaf(a.x, k.z, s02); s03 = fmaf(a.x, k.w, s03);
            s10 = fmaf(a.y, k.x, s10); s11 = fmaf(a.y, k.y, s11);
            s12 = fmaf(a.y, k.z, s12); s13 = fmaf(a.y, k.w, s13);
            s20 = fmaf(a.z, k.x, s20); s21 = fmaf(a.z, k.y, s21);
            s22 = fmaf(a.z, k.z, s22); s23 = fmaf(a.z, k.w, s23);
            s30 = fmaf(a.w, k.x, s30); s31 = fmaf(a.w, k.y, s31);
            s32 = fmaf(a.w, k.z, s32); s33 = fmaf(a.w, k.w, s33);
        }
        {
            const bool diag = (kb == qt);
            float sv[4][4] = {{s00,s01,s02,s03},{s10,s11,s12,s13},
                              {s20,s21,s22,s23},{s30,s31,s32,s33}};
            #pragma unroll
            for (int i = 0; i < 4; i++)
                #pragma unroll
                for (int j = 0; j < 4; j++) {
                    float v = sv[i][j] * sc_qk;
                    if (diag && (tx*4 + j > ty*4 + i)) v = -INFINITY;
                    sP[(ty*4 + i)*65 + tx*4 + j] = v;
                }
        }
        __syncthreads();

        // ---- online softmax stats: one thread per query row ----
        if (tid < 64) {
            float* row = sP + tid*65;
            float mold = sM[tid];
            float mx = mold;
            #pragma unroll 8
            for (int j = 0; j < 64; j++) mx = fmaxf(mx, row[j]);
            float scl = __expf(mold - mx);     // 0 when mold == -inf
            float sum = 0.f;
            #pragma unroll 8
            for (int j = 0; j < 64; j++) {
                float e = __expf(row[j] - mx);
                row[j] = e;
                sum += e;
            }
            sL[tid]  = sL[tid] * scl + sum;
            sM[tid]  = mx;
            sSc[tid] = scl;
        }
        __syncthreads();

        // ---- rescale + O += P V  (4 rows x 8 cols per thread) ----
        float f0 = sSc[ty*4+0], f1 = sSc[ty*4+1];
        float f2 = sSc[ty*4+2], f3 = sSc[ty*4+3];
        #pragma unroll
        for (int j = 0; j < 8; j++) {
            accO[0][j] *= f0; accO[1][j] *= f1;
            accO[2][j] *= f2; accO[3][j] *= f3;
        }
        #pragma unroll 2
        for (int k = 0; k < 64; k++) {
            float p0 = sP[(ty*4+0)*65 + k];
            float p1 = sP[(ty*4+1)*65 + k];
            float p2 = sP[(ty*4+2)*65 + k];
            float p3 = sP[(ty*4+3)*65 + k];
            float4 v0 = *(const float4*)&sV[k*128 + tx*8];
            float4 v1 = *(const float4*)&sV[k*128 + tx*8 + 4];
            accO[0][0]=fmaf(p0,v0.x,accO[0][0]); accO[0][1]=fmaf(p0,v0.y,accO[0][1]);
            accO[0][2]=fmaf(p0,v0.z,accO[0][2]); accO[0][3]=fmaf(p0,v0.w,accO[0][3]);
            accO[0][4]=fmaf(p0,v1.x,accO[0][4]); accO[0][5]=fmaf(p0,v1.y,accO[0][5]);
            accO[0][6]=fmaf(p0,v1.z,accO[0][6]); accO[0][7]=fmaf(p0,v1.w,accO[0][7]);
            accO[1][0]=fmaf(p1,v0.x,accO[1][0]); accO[1][1]=fmaf(p1,v0.y,accO[1][1]);
            accO[1][2]=fmaf(p1,v0.z,accO[1][2]); accO[1][3]=fmaf(p1,v0.w,accO[1][3]);
            accO[1][4]=fmaf(p1,v1.x,accO[1][4]); accO[1][5]=fmaf(p1,v1.y,accO[1][5]);
            accO[1][6]=fmaf(p1,v1.z,accO[1][6]); accO[1][7]=fmaf(p1,v1.w,accO[1][7]);
            accO[2][0]=fmaf(p2,v0.x,accO[2][0]); accO[2][1]=fmaf(p2,v0.y,accO[2][1]);
            accO[2][2]=fmaf(p2,v0.z,accO[2][2]); accO[2][3]=fmaf(p2,v0.w,accO[2][3]);
            accO[2][4]=fmaf(p2,v1.x,accO[2][4]); accO[2][5]=fmaf(p2,v1.y,accO[2][5]);
            accO[2][6]=fmaf(p2,v1.z,accO[2][6]); accO[2][7]=fmaf(p2,v1.w,accO[2][7]);
            accO[3][0]=fmaf(p3,v0.x,accO[3][0]); accO[3][1]=fmaf(p3,v0.y,accO[3][1]);
            accO[3][2]=fmaf(p3,v0.z,accO[3][2]); accO[3][3]=fmaf(p3,v0.w,accO[3][3]);
            accO[3][4]=fmaf(p3,v1.x,accO[3][4]); accO[3][5]=fmaf(p3,v1.y,accO[3][5]);
            accO[3][6]=fmaf(p3,v1.z,accO[3][6]); accO[3][7]=fmaf(p3,v1.w,accO[3][7]);
        }
    }

    #pragma unroll
    for (int i = 0; i < 4; i++) {
        float inv = 1.f / sL[ty*4 + i];
        float* outp = g_O + (long)(rowbase + q0 + ty*4 + i) * D_ + h*HD_ + tx*8;
        #pragma unroll
        for (int j = 0; j < 8; j++) outp[j] = accO[i][j] * inv;
    }
}

// ------------------------------------------------------------------
// Launcher
// ------------------------------------------------------------------
extern "C" void kernel_launch(void* const* d_in, const int* in_sizes, int n_in,
                              void* d_out, int out_size)
{
    const float* x   = (const float*)d_in[0];
    const float* Wq  = (const float*)d_in[1];
    const float* bq  = (const float*)d_in[2];
    const float* Wkv = (const float*)d_in[3];
    const float* bkv = (const float*)d_in[4];
    const float* Wkr = (const float*)d_in[5];
    const float* bkr = (const float*)d_in[6];
    const float* Wku = (const float*)d_in[7];
    const float* bku = (const float*)d_in[8];
    const float* Wvu = (const float*)d_in[9];
    const float* bvu = (const float*)d_in[10];
    const float* Wo  = (const float*)d_in[11];
    const float* bo  = (const float*)d_in[12];
    float* out = (float*)d_out;

    void *pQ, *pKV, *pKR, *pKC, *pV, *pO;
    cudaGetSymbolAddress(&pQ,  g_Q);
    cudaGetSymbolAddress(&pKV, g_KV);
    cudaGetSymbolAddress(&pKR, g_KR);
    cudaGetSymbolAddress(&pKC, g_KC);
    cudaGetSymbolAddress(&pV,  g_V);
    cudaGetSymbolAddress(&pO,  g_O);

    const dim3 blk(256);

    // Q = x Wq^T + bq          (4096 x 2048, K=2048)
    sgemm_nt_bias<<<dim3(16, 32), blk>>>(x, D_, Wq, D_, bq,
                                         (float*)pQ, D_, M_, D_, D_);
    // KV = x Wkv^T + bkv       (4096 x 1024, K=2048)
    sgemm_nt_bias<<<dim3(8, 32), blk>>>(x, D_, Wkv, D_, bkv,
                                        (float*)pKV, 2*LAT_, M_, 2*LAT_, D_);
    // KR = x Wkr^T + bkr       (4096 x 64, K=2048)
    sgemm_nt_bias<<<dim3(1, 32), blk>>>(x, D_, Wkr, D_, bkr,
                                        (float*)pKR, RD_, M_, RD_, D_);
    rope_kr_kernel<<<M_, 32>>>();

    // KC = KV[:, :512] Wku^T + bku   (4096 x 1024, K=512)
    sgemm_nt_bias<<<dim3(8, 32), blk>>>((const float*)pKV, 2*LAT_, Wku, LAT_, bku,
                                        (float*)pKC, H_*CD_, M_, H_*CD_, LAT_);
    // V  = KV[:, 512:] Wvu^T + bvu   (4096 x 2048, K=512)
    sgemm_nt_bias<<<dim3(16, 32), blk>>>((const float*)pKV + LAT_, 2*LAT_, Wvu, LAT_, bvu,
                                         (float*)pV, D_, M_, D_, LAT_);

    rope_q_kernel<<<M_, 512>>>();

    cudaFuncSetAttribute(flash_kernel,
                         cudaFuncAttributeMaxDynamicSharedMemorySize, FL_SMEM_BYTES);
    flash_kernel<<<dim3(32, 32), 256, FL_SMEM_BYTES>>>();

    // out = O Wo^T + bo        (4096 x 2048, K=2048)
    sgemm_nt_bias<<<dim3(16, 32), blk>>>((const float*)pO, D_, Wo, D_, bo,
                                         out, D_, M_, D_, D_);
}

// round 4
// speedup vs baseline: 1.0605x; 1.0605x over previous
#include <cuda_runtime.h>
#include <math.h>

#define B_   2
#define T_   2048
#define D_   2048
#define H_   16
#define HD_  128
#define LAT_ 512
#define RD_  64
#define CD_  64
#define M_   (B_*T_)   // 4096 rows total

typedef unsigned long long ull;

// ---- packed f32x2 helpers (sm_103a FFMA2 path) ----
__device__ __forceinline__ ull ffma2(ull a, ull b, ull c) {
    ull d;
    asm("fma.rn.f32x2 %0, %1, %2, %3;" : "=l"(d) : "l"(a), "l"(b), "l"(c));
    return d;
}
__device__ __forceinline__ ull fmul2(ull a, ull b) {
    ull d;
    asm("mul.rn.f32x2 %0, %1, %2;" : "=l"(d) : "l"(a), "l"(b));
    return d;
}
__device__ __forceinline__ ull splat2(float x) {
    ull r;
    asm("mov.b64 %0, {%1, %1};" : "=l"(r) : "f"(x));
    return r;
}
__device__ __forceinline__ float2 unpack2(ull v) {
    float2 f;
    asm("mov.b64 {%0, %1}, %2;" : "=f"(f.x), "=f"(f.y) : "l"(v));
    return f;
}

// ------------------------------------------------------------------
// Scratch (device globals: the sanctioned alloc-free workaround)
// ------------------------------------------------------------------
__device__ float g_Q [M_*D_];        // (B,T,H,HD) flattened rows x 2048
__device__ float g_KV[M_*2*LAT_];    // rows x 1024 : [k_lat | v_lat]
__device__ float g_KR[M_*RD_];       // rows x 64   : roped shared key
__device__ float g_KC[M_*H_*CD_];    // rows x 1024 : per-head content key
__device__ float g_V [M_*D_];        // rows x 2048
__device__ float g_O [M_*D_];        // attention output rows x 2048

// ------------------------------------------------------------------
// fp32 GEMM (FFMA2 core):  C[M,N] = A[M,K](lda) * W[N,K](ldb)^T + bias[N]
// 128x128 tile, BK=16, 256 threads, 8x8 per thread.
// Register-prefetch + double-buffered smem: one sync per K-step.
// ------------------------------------------------------------------
__global__ __launch_bounds__(256) void sgemm_nt_bias(
    const float* __restrict__ A, int lda,
    const float* __restrict__ W, int ldb,
    const float* __restrict__ bias,
    float* __restrict__ C, int ldc,
    int Mdim, int Ndim, int Kdim)
{
    __shared__ float As[2][16][132];  // [buf][k][m]
    __shared__ float Bs[2][16][132];  // [buf][k][n]

    const int bm  = blockIdx.y * 128;
    const int bn  = blockIdx.x * 128;
    const int tid = threadIdx.x;
    const int tx  = tid & 15;      // n sub-tile
    const int ty  = tid >> 4;      // m sub-tile
    const int lr  = tid >> 2;      // load row 0..63
    const int lc  = (tid & 3) << 2;// load col 0,4,8,12

    ull acc2[8][4];
    #pragma unroll
    for (int i = 0; i < 8; i++)
        #pragma unroll
        for (int jp = 0; jp < 4; jp++) acc2[i][jp] = 0ull;

    float4 pa[2], pb[2];           // prefetch registers

    // ---- prologue: fetch k0 = 0 ----
    #pragma unroll
    for (int half = 0; half < 2; half++) {
        const int row = lr + half * 64;
        const int m = bm + row;
        pa[half] = make_float4(0.f, 0.f, 0.f, 0.f);
        if (m < Mdim) pa[half] = *(const float4*)(A + (long)m * lda + lc);
        const int n = bn + row;
        pb[half] = make_float4(0.f, 0.f, 0.f, 0.f);
        if (n < Ndim) pb[half] = *(const float4*)(W + (long)n * ldb + lc);
    }
    #pragma unroll
    for (int half = 0; half < 2; half++) {
        const int row = lr + half * 64;
        As[0][lc+0][row] = pa[half].x; As[0][lc+1][row] = pa[half].y;
        As[0][lc+2][row] = pa[half].z; As[0][lc+3][row] = pa[half].w;
        Bs[0][lc+0][row] = pb[half].x; Bs[0][lc+1][row] = pb[half].y;
        Bs[0][lc+2][row] = pb[half].z; Bs[0][lc+3][row] = pb[half].w;
    }
    __syncthreads();

    int buf = 0;
    for (int k0 = 16; k0 < Kdim; k0 += 16) {
        // ---- issue global loads for next tile ----
        #pragma unroll
        for (int half = 0; half < 2; half++) {
            const int row = lr + half * 64;
            const int m = bm + row;
            pa[half] = make_float4(0.f, 0.f, 0.f, 0.f);
            if (m < Mdim) pa[half] = *(const float4*)(A + (long)m * lda + k0 + lc);
            const int n = bn + row;
            pb[half] = make_float4(0.f, 0.f, 0.f, 0.f);
            if (n < Ndim) pb[half] = *(const float4*)(W + (long)n * ldb + k0 + lc);
        }

        // ---- compute on current buffer (overlaps the loads above) ----
        #pragma unroll
        for (int kk = 0; kk < 16; kk++) {
            float a[8];
            *(float4*)&a[0]  = *(const float4*)&As[buf][kk][ty*8];
            *(float4*)&a[4]  = *(const float4*)&As[buf][kk][ty*8+4];
            ulonglong2 bA = *(const ulonglong2*)&Bs[buf][kk][tx*8];
            ulonglong2 bB = *(const ulonglong2*)&Bs[buf][kk][tx*8+4];
            ull bb2[4] = {bA.x, bA.y, bB.x, bB.y};
            #pragma unroll
            for (int i = 0; i < 8; i++) {
                ull aa = splat2(a[i]);
                #pragma unroll
                for (int jp = 0; jp < 4; jp++)
                    acc2[i][jp] = ffma2(aa, bb2[jp], acc2[i][jp]);
            }
        }

        // ---- store prefetched tile into the other buffer ----
        const int nb = buf ^ 1;
        #pragma unroll
        for (int half = 0; half < 2; half++) {
            const int row = lr + half * 64;
            As[nb][lc+0][row] = pa[half].x; As[nb][lc+1][row] = pa[half].y;
            As[nb][lc+2][row] = pa[half].z; As[nb][lc+3][row] = pa[half].w;
            Bs[nb][lc+0][row] = pb[half].x; Bs[nb][lc+1][row] = pb[half].y;
            Bs[nb][lc+2][row] = pb[half].z; Bs[nb][lc+3][row] = pb[half].w;
        }
        __syncthreads();
        buf = nb;
    }

    // ---- epilogue compute on final buffer ----
    #pragma unroll
    for (int kk = 0; kk < 16; kk++) {
        float a[8];
        *(float4*)&a[0]  = *(const float4*)&As[buf][kk][ty*8];
        *(float4*)&a[4]  = *(const float4*)&As[buf][kk][ty*8+4];
        ulonglong2 bA = *(const ulonglong2*)&Bs[buf][kk][tx*8];
        ulonglong2 bB = *(const ulonglong2*)&Bs[buf][kk][tx*8+4];
        ull bb2[4] = {bA.x, bA.y, bB.x, bB.y};
        #pragma unroll
        for (int i = 0; i < 8; i++) {
            ull aa = splat2(a[i]);
            #pragma unroll
            for (int jp = 0; jp < 4; jp++)
                acc2[i][jp] = ffma2(aa, bb2[jp], acc2[i][jp]);
        }
    }

    #pragma unroll
    for (int i = 0; i < 8; i++) {
        const int m = bm + ty*8 + i;
        if (m >= Mdim) continue;
        #pragma unroll
        for (int jp = 0; jp < 4; jp++) {
            float2 c = unpack2(acc2[i][jp]);
            const int n0 = bn + tx*8 + jp*2;
            if (n0 < Ndim)     C[(long)m * ldc + n0]     = c.x + bias[n0];
            if (n0 + 1 < Ndim) C[(long)m * ldc + n0 + 1] = c.y + bias[n0+1];
        }
    }
}

// ------------------------------------------------------------------
// RoPE (rotate-half). inv_freq = 10000^(-2j/64); pos = row % T.
// ------------------------------------------------------------------
__device__ __forceinline__ void rope_pair(int pos, int j, float& x1, float& x2)
{
    const float LOG2_THETA = 13.287712379549449f;   // log2(10000)
    float e   = (float)(2 * j) * (1.0f / (float)RD_);
    float inv = exp2f(-e * LOG2_THETA);
    float ang = (float)pos * inv;
    float s, c;
    sincosf(ang, &s, &c);
    float a = x1, b = x2;
    x1 = a * c - b * s;
    x2 = b * c + a * s;
}

__global__ void rope_kr_kernel()
{
    int r = blockIdx.x;       // 0..4095
    int j = threadIdx.x;      // 0..31
    int pos = r & (T_ - 1);
    float* p = g_KR + (long)r * RD_;
    float x1 = p[j], x2 = p[j + 32];
    rope_pair(pos, j, x1, x2);
    p[j] = x1; p[j + 32] = x2;
}

__global__ void rope_q_kernel()
{
    int r   = blockIdx.x;          // 0..4095
    int tid = threadIdx.x;         // 0..511
    int h = tid >> 5, j = tid & 31;
    int pos = r & (T_ - 1);
    float* p = g_Q + (long)r * D_ + h * HD_ + CD_;
    float x1 = p[j], x2 = p[j + 32];
    rope_pair(pos, j, x1, x2);
    p[j] = x1; p[j + 32] = x2;
}

// ------------------------------------------------------------------
// fp32 causal flash attention (FFMA2 core).
// One CTA = (b,h) pair x 64-query tile.
// K assembled on the fly from g_KC (content, d<64) and g_KR (rope).
// ------------------------------------------------------------------
#define FL_SMEM_FLOATS (2*128*68 + 64*128 + 64*65 + 3*64)
#define FL_SMEM_BYTES  (FL_SMEM_FLOATS * 4)

__global__ __launch_bounds__(256) void flash_kernel()
{
    extern __shared__ float sm[];
    float* sQt = sm;                   // [128][68]  (d-major, transposed)
    float* sKt = sQt + 128*68;         // [128][68]
    float* sV  = sKt + 128*68;         // [64][128]
    float* sP  = sV  + 64*128;         // [64][65]   scores then probs
    float* sM  = sP  + 64*65;          // [64]
    float* sL  = sM  + 64;             // [64]
    float* sSc = sL  + 64;             // [64]

    const int qt = 31 - blockIdx.x;    // big tiles scheduled first
    const int pr = blockIdx.y;         // 0..31  (b,h)
    const int b  = pr >> 4, h = pr & 15;
    const int tid = threadIdx.x;
    const int tx = tid & 15, ty = tid >> 4;
    const int q0 = qt * 64;
    const int rowbase = b * T_;

    #pragma unroll 8
    for (int idx = tid; idx < 64*128; idx += 256) {
        int qi = idx >> 7, d = idx & 127;
        sQt[d*68 + qi] = g_Q[(long)(rowbase + q0 + qi) * D_ + h*HD_ + d];
    }
    if (tid < 64) { sM[tid] = -INFINITY; sL[tid] = 0.f; }

    ull accO2[4][4];
    #pragma unroll
    for (int i = 0; i < 4; i++)
        #pragma unroll
        for (int jp = 0; jp < 4; jp++) accO2[i][jp] = 0ull;

    const float sc_qk = 0.08838834764831845f;   // 1/sqrt(128)

    for (int kb = 0; kb <= qt; kb++) {
        const int k0 = kb * 64;
        __syncthreads();    // previous consumers done before overwrite
        #pragma unroll 8
        for (int idx = tid; idx < 64*128; idx += 256) {
            int ki = idx >> 7, d = idx & 127;
            int r  = rowbase + k0 + ki;
            float kv = (d < CD_) ? g_KC[(long)r * (H_*CD_) + h*CD_ + d]
                                 : g_KR[(long)r * RD_ + (d - CD_)];
            sKt[d*68 + ki]  = kv;
            sV [ki*128 + d] = g_V[(long)r * D_ + h*HD_ + d];
        }
        __syncthreads();

        // ---- S = Q K^T  (4 rows x 4 cols per thread, packed col-pairs) ----
        ull s2[4][2];
        #pragma unroll
        for (int i = 0; i < 4; i++) { s2[i][0] = 0ull; s2[i][1] = 0ull; }
        #pragma unroll 4
        for (int d = 0; d < 128; d++) {
            float4 a = *(const float4*)&sQt[d*68 + ty*4];
            ulonglong2 kp = *(const ulonglong2*)&sKt[d*68 + tx*4];
            ull a0 = splat2(a.x), a1 = splat2(a.y);
            ull a2 = splat2(a.z), a3 = splat2(a.w);
            s2[0][0] = ffma2(a0, kp.x, s2[0][0]); s2[0][1] = ffma2(a0, kp.y, s2[0][1]);
            s2[1][0] = ffma2(a1, kp.x, s2[1][0]); s2[1][1] = ffma2(a1, kp.y, s2[1][1]);
            s2[2][0] = ffma2(a2, kp.x, s2[2][0]); s2[2][1] = ffma2(a2, kp.y, s2[2][1]);
            s2[3][0] = ffma2(a3, kp.x, s2[3][0]); s2[3][1] = ffma2(a3, kp.y, s2[3][1]);
        }
        {
            const bool diag = (kb == qt);
            #pragma unroll
            for (int i = 0; i < 4; i++) {
                #pragma unroll
                for (int jp = 0; jp < 2; jp++) {
                    float2 sv = unpack2(s2[i][jp]);
                    int j0 = tx*4 + jp*2;
                    float v0 = sv.x * sc_qk;
                    float v1 = sv.y * sc_qk;
                    if (diag && (j0     > ty*4 + i)) v0 = -INFINITY;
                    if (diag && (j0 + 1 > ty*4 + i)) v1 = -INFINITY;
                    sP[(ty*4 + i)*65 + j0]     = v0;
                    sP[(ty*4 + i)*65 + j0 + 1] = v1;
                }
            }
        }
        __syncthreads();

        // ---- online softmax stats: one thread per query row ----
        if (tid < 64) {
            float* row = sP + tid*65;
            float mold = sM[tid];
            float mx = mold;
            #pragma unroll 8
            for (int j = 0; j < 64; j++) mx = fmaxf(mx, row[j]);
            float scl = __expf(mold - mx);     // 0 when mold == -inf
            float sum = 0.f;
            #pragma unroll 8
            for (int j = 0; j < 64; j++) {
                float e = __expf(row[j] - mx);
                row[j] = e;
                sum += e;
            }
            sL[tid]  = sL[tid] * scl + sum;
            sM[tid]  = mx;
            sSc[tid] = scl;
        }
        __syncthreads();

        // ---- rescale + O += P V  (4 rows x 8 cols per thread, packed) ----
        {
            ull f0 = splat2(sSc[ty*4+0]), f1 = splat2(sSc[ty*4+1]);
            ull f2 = splat2(sSc[ty*4+2]), f3 = splat2(sSc[ty*4+3]);
            #pragma unroll
            for (int jp = 0; jp < 4; jp++) {
                accO2[0][jp] = fmul2(accO2[0][jp], f0);
                accO2[1][jp] = fmul2(accO2[1][jp], f1);
                accO2[2][jp] = fmul2(accO2[2][jp], f2);
                accO2[3][jp] = fmul2(accO2[3][jp], f3);
            }
        }
        #pragma unroll 2
        for (int k = 0; k < 64; k++) {
            ull p0 = splat2(sP[(ty*4+0)*65 + k]);
            ull p1 = splat2(sP[(ty*4+1)*65 + k]);
            ull p2 = splat2(sP[(ty*4+2)*65 + k]);
            ull p3 = splat2(sP[(ty*4+3)*65 + k]);
            ulonglong2 v0 = *(const ulonglong2*)&sV[k*128 + tx*8];
            ulonglong2 v1 = *(const ulonglong2*)&sV[k*128 + tx*8 + 4];
            accO2[0][0] = ffma2(p0, v0.x, accO2[0][0]);
            accO2[0][1] = ffma2(p0, v0.y, accO2[0][1]);
            accO2[0][2] = ffma2(p0, v1.x, accO2[0][2]);
            accO2[0][3] = ffma2(p0, v1.y, accO2[0][3]);
            accO2[1][0] = ffma2(p1, v0.x, accO2[1][0]);
            accO2[1][1] = ffma2(p1, v0.y, accO2[1][1]);
            accO2[1][2] = ffma2(p1, v1.x, accO2[1][2]);
            accO2[1][3] = ffma2(p1, v1.y, accO2[1][3]);
            accO2[2][0] = ffma2(p2, v0.x, accO2[2][0]);
            accO2[2][1] = ffma2(p2, v0.y, accO2[2][1]);
            accO2[2][2] = ffma2(p2, v1.x, accO2[2][2]);
            accO2[2][3] = ffma2(p2, v1.y, accO2[2][3]);
            accO2[3][0] = ffma2(p3, v0.x, accO2[3][0]);
            accO2[3][1] = ffma2(p3, v0.y, accO2[3][1]);
            accO2[3][2] = ffma2(p3, v1.x, accO2[3][2]);
            accO2[3][3] = ffma2(p3, v1.y, accO2[3][3]);
        }
    }

    #pragma unroll
    for (int i = 0; i < 4; i++) {
        float inv = 1.f / sL[ty*4 + i];
        float* outp = g_O + (long)(rowbase + q0 + ty*4 + i) * D_ + h*HD_ + tx*8;
        #pragma unroll
        for (int jp = 0; jp < 4; jp++) {
            float2 c = unpack2(accO2[i][jp]);
            outp[jp*2]     = c.x * inv;
            outp[jp*2 + 1] = c.y * inv;
        }
    }
}

// ------------------------------------------------------------------
// Launcher
// ------------------------------------------------------------------
extern "C" void kernel_launch(void* const* d_in, const int* in_sizes, int n_in,
                              void* d_out, int out_size)
{
    const float* x   = (const float*)d_in[0];
    const float* Wq  = (const float*)d_in[1];
    const float* bq  = (const float*)d_in[2];
    const float* Wkv = (const float*)d_in[3];
    const float* bkv = (const float*)d_in[4];
    const float* Wkr = (const float*)d_in[5];
    const float* bkr = (const float*)d_in[6];
    const float* Wku = (const float*)d_in[7];
    const float* bku = (const float*)d_in[8];
    const float* Wvu = (const float*)d_in[9];
    const float* bvu = (const float*)d_in[10];
    const float* Wo  = (const float*)d_in[11];
    const float* bo  = (const float*)d_in[12];
    float* out = (float*)d_out;

    void *pQ, *pKV, *pKR, *pKC, *pV, *pO;
    cudaGetSymbolAddress(&pQ,  g_Q);
    cudaGetSymbolAddress(&pKV, g_KV);
    cudaGetSymbolAddress(&pKR, g_KR);
    cudaGetSymbolAddress(&pKC, g_KC);
    cudaGetSymbolAddress(&pV,  g_V);
    cudaGetSymbolAddress(&pO,  g_O);

    const dim3 blk(256);

    // Q = x Wq^T + bq          (4096 x 2048, K=2048)
    sgemm_nt_bias<<<dim3(16, 32), blk>>>(x, D_, Wq, D_, bq,
                                         (float*)pQ, D_, M_, D_, D_);
    // KV = x Wkv^T + bkv       (4096 x 1024, K=2048)
    sgemm_nt_bias<<<dim3(8, 32), blk>>>(x, D_, Wkv, D_, bkv,
                                        (float*)pKV, 2*LAT_, M_, 2*LAT_, D_);
    // KR = x Wkr^T + bkr       (4096 x 64, K=2048)
    sgemm_nt_bias<<<dim3(1, 32), blk>>>(x, D_, Wkr, D_, bkr,
                                        (float*)pKR, RD_, M_, RD_, D_);
    rope_kr_kernel<<<M_, 32>>>();

    // KC = KV[:, :512] Wku^T + bku   (4096 x 1024, K=512)
    sgemm_nt_bias<<<dim3(8, 32), blk>>>((const float*)pKV, 2*LAT_, Wku, LAT_, bku,
                                        (float*)pKC, H_*CD_, M_, H_*CD_, LAT_);
    // V  = KV[:, 512:] Wvu^T + bvu   (4096 x 2048, K=512)
    sgemm_nt_bias<<<dim3(16, 32), blk>>>((const float*)pKV + LAT_, 2*LAT_, Wvu, LAT_, bvu,
                                         (float*)pV, D_, M_, D_, LAT_);

    rope_q_kernel<<<M_, 512>>>();

    cudaFuncSetAttribute(flash_kernel,
                         cudaFuncAttributeMaxDynamicSharedMemorySize, FL_SMEM_BYTES);
    flash_kernel<<<dim3(32, 32), 256, FL_SMEM_BYTES>>>();

    // out = O Wo^T + bo        (4096 x 2048, K=2048)
    sgemm_nt_bias<<<dim3(16, 32), blk>>>((const float*)pO, D_, Wo, D_, bo,
                                         out, D_, M_, D_, D_);
}

// round 8
// speedup vs baseline: 1.5082x; 1.4222x over previous
#include <cuda_runtime.h>
#include <cuda_bf16.h>
#include <math.h>
#include <stdint.h>

#define B_   2
#define T_   2048
#define D_   2048
#define H_   16
#define HD_  128
#define LAT_ 512
#define RD_  64
#define CD_  64
#define M_   (B_*T_)   // 4096 rows total

typedef unsigned long long ull;

// ================= packed f32x2 helpers (flash kernel) =================
__device__ __forceinline__ ull ffma2(ull a, ull b, ull c) {
    ull d;
    asm("fma.rn.f32x2 %0, %1, %2, %3;" : "=l"(d) : "l"(a), "l"(b), "l"(c));
    return d;
}
__device__ __forceinline__ ull fmul2(ull a, ull b) {
    ull d;
    asm("mul.rn.f32x2 %0, %1, %2;" : "=l"(d) : "l"(a), "l"(b));
    return d;
}
__device__ __forceinline__ ull splat2(float x) {
    ull r;
    asm("mov.b64 %0, {%1, %1};" : "=l"(r) : "f"(x));
    return r;
}
__device__ __forceinline__ float2 unpack2(ull v) {
    float2 f;
    asm("mov.b64 {%0, %1}, %2;" : "=f"(f.x), "=f"(f.y) : "l"(v));
    return f;
}

// ================= scratch =================
__device__ float g_Q [M_*D_];
__device__ float g_KV[M_*2*LAT_];
__device__ float g_KR[M_*RD_];
__device__ float g_KC[M_*H_*CD_];
__device__ float g_V [M_*D_];
__device__ float g_O [M_*D_];

__device__ __nv_bfloat16 g_xh [M_*D_],        g_xl [M_*D_];
__device__ __nv_bfloat16 g_Wqh [D_*D_],       g_Wql [D_*D_];
__device__ __nv_bfloat16 g_Wkvh[2*LAT_*D_],   g_Wkvl[2*LAT_*D_];
__device__ __nv_bfloat16 g_Wkrh[RD_*D_],      g_Wkrl[RD_*D_];
__device__ __nv_bfloat16 g_Wkuh[H_*CD_*LAT_], g_Wkul[H_*CD_*LAT_];
__device__ __nv_bfloat16 g_Wvuh[D_*LAT_],     g_Wvul[D_*LAT_];
__device__ __nv_bfloat16 g_Woh [D_*D_],       g_Wol [D_*D_];
__device__ __nv_bfloat16 g_KVh [M_*2*LAT_],   g_KVl [M_*2*LAT_];
__device__ __nv_bfloat16 g_Oh  [M_*D_],       g_Ol  [M_*D_];

// ================= fp32 -> (hi, lo) bf16 split =================
__global__ __launch_bounds__(256) void split_f32_bf16(
    const float* __restrict__ src,
    __nv_bfloat16* __restrict__ hi, __nv_bfloat16* __restrict__ lo, int n)
{
    int i = (blockIdx.x * 256 + threadIdx.x) * 4;
    if (i >= n) return;
    float4 v = *(const float4*)(src + i);
    __nv_bfloat16 h0 = __float2bfloat16(v.x), h1 = __float2bfloat16(v.y);
    __nv_bfloat16 h2 = __float2bfloat16(v.z), h3 = __float2bfloat16(v.w);
    __nv_bfloat16 l0 = __float2bfloat16(v.x - __bfloat162float(h0));
    __nv_bfloat16 l1 = __float2bfloat16(v.y - __bfloat162float(h1));
    __nv_bfloat16 l2 = __float2bfloat16(v.z - __bfloat162float(h2));
    __nv_bfloat16 l3 = __float2bfloat16(v.w - __bfloat162float(h3));
    __nv_bfloat162* hp = (__nv_bfloat162*)(hi + i);
    __nv_bfloat162* lp = (__nv_bfloat162*)(lo + i);
    hp[0] = __nv_bfloat162(h0, h1); hp[1] = __nv_bfloat162(h2, h3);
    lp[0] = __nv_bfloat162(l0, l1); lp[1] = __nv_bfloat162(l2, l3);
}

// ================= HMMA helpers (base ISA, legal on sm_103) =================
__device__ __forceinline__ void mma16816(float* c, const uint32_t* a, const uint32_t* b)
{
    asm volatile(
        "mma.sync.aligned.m16n8k16.row.col.f32.bf16.bf16.f32 "
        "{%0,%1,%2,%3}, {%4,%5,%6,%7}, {%8,%9}, {%0,%1,%2,%3};"
        : "+f"(c[0]), "+f"(c[1]), "+f"(c[2]), "+f"(c[3])
        : "r"(a[0]), "r"(a[1]), "r"(a[2]), "r"(a[3]), "r"(b[0]), "r"(b[1]));
}

// ================= HMMA 3-pass split-bf16 GEMM =================
// C[M,N] = Ah·Bh^T + Ah·Bl^T + Al·Bh^T + bias  (fp32 acc)
// A[M,K] bf16 hi/lo (lda, col offset aoff), B = W[N,K] bf16 hi/lo.
// Tile: 128 x BN, BK=32, 256 threads / 8 warps.
template<int BN>
__global__ __launch_bounds__(256) void gemm_hmma_3p(
    const __nv_bfloat16* __restrict__ Ah, const __nv_bfloat16* __restrict__ Al,
    int lda, int aoff,
    const __nv_bfloat16* __restrict__ Bh, const __nv_bfloat16* __restrict__ Bl,
    const float* __restrict__ bias,
    float* __restrict__ C, int ldc, int Kdim)
{
    constexpr int KP = 40;            // padded K stride (bank-conflict-free frags)
    constexpr int GC = BN / 32;       // warp grid cols (4 or 2)
    constexpr int GR = 8 / GC;        // warp grid rows (2 or 4)
    constexpr int WM = 128 / GR;      // warp tile M (64 or 32)
    constexpr int MA = WM / 16;       // m-atoms per warp (4 or 2)

    __shared__ __nv_bfloat16 sA[2][128][KP];   // [hi/lo][m][k]
    __shared__ __nv_bfloat16 sB[2][BN][KP];    // [hi/lo][n][k]

    const int tid  = threadIdx.x;
    const int wid  = tid >> 5, lane = tid & 31;
    const int g    = lane >> 2, t = lane & 3;
    const int bm   = blockIdx.y * 128;
    const int bn   = blockIdx.x * BN;
    const int wm   = (wid / GC) * WM;
    const int wn   = (wid % GC) * 32;

    float acc[MA][4][4];
    #pragma unroll
    for (int im = 0; im < MA; im++)
        #pragma unroll
        for (int in_ = 0; in_ < 4; in_++)
            #pragma unroll
            for (int r = 0; r < 4; r++) acc[im][in_][r] = 0.f;

    for (int k0 = 0; k0 < Kdim; k0 += 32) {
        __syncthreads();
        // ---- A tile: 128 x 32, hi + lo (8 bf16 per thread per iter) ----
        #pragma unroll
        for (int it = 0; it < 2; it++) {
            int idx = (tid + it * 256) * 8;
            int row = idx >> 5, col = idx & 31;
            long go = (long)(bm + row) * lda + aoff + k0 + col;
            *(uint4*)&sA[0][row][col] = *(const uint4*)(Ah + go);
            *(uint4*)&sA[1][row][col] = *(const uint4*)(Al + go);
        }
        // ---- B tile: BN x 32, hi + lo ----
        #pragma unroll
        for (int it = 0; it < BN / 64; it++) {
            int idx = (tid + it * 256) * 8;
            int row = idx >> 5, col = idx & 31;
            long go = (long)(bn + row) * Kdim + k0 + col;
            *(uint4*)&sB[0][row][col] = *(const uint4*)(Bh + go);
            *(uint4*)&sB[1][row][col] = *(const uint4*)(Bl + go);
        }
        __syncthreads();

        #pragma unroll
        for (int ks = 0; ks < 2; ks++) {
            const int kb = ks * 16;
            uint32_t ah[MA][4], al[MA][4];
            #pragma unroll
            for (int im = 0; im < MA; im++) {
                int r0 = wm + im * 16 + g;
                ah[im][0] = *(const uint32_t*)&sA[0][r0    ][kb + t*2];
                ah[im][1] = *(const uint32_t*)&sA[0][r0 + 8][kb + t*2];
                ah[im][2] = *(const uint32_t*)&sA[0][r0    ][kb + 8 + t*2];
                ah[im][3] = *(const uint32_t*)&sA[0][r0 + 8][kb + 8 + t*2];
                al[im][0] = *(const uint32_t*)&sA[1][r0    ][kb + t*2];
                al[im][1] = *(const uint32_t*)&sA[1][r0 + 8][kb + t*2];
                al[im][2] = *(const uint32_t*)&sA[1][r0    ][kb + 8 + t*2];
                al[im][3] = *(const uint32_t*)&sA[1][r0 + 8][kb + 8 + t*2];
            }
            uint32_t bh[4][2], bl[4][2];
            #pragma unroll
            for (int in_ = 0; in_ < 4; in_++) {
                int r = wn + in_ * 8 + g;
                bh[in_][0] = *(const uint32_t*)&sB[0][r][kb + t*2];
                bh[in_][1] = *(const uint32_t*)&sB[0][r][kb + 8 + t*2];
                bl[in_][0] = *(const uint32_t*)&sB[1][r][kb + t*2];
                bl[in_][1] = *(const uint32_t*)&sB[1][r][kb + 8 + t*2];
            }
            #pragma unroll
            for (int im = 0; im < MA; im++)
                #pragma unroll
                for (int in_ = 0; in_ < 4; in_++) {
                    mma16816(acc[im][in_], ah[im], bh[in_]);
                    mma16816(acc[im][in_], ah[im], bl[in_]);
                    mma16816(acc[im][in_], al[im], bh[in_]);
                }
        }
    }

    // ---- epilogue: acc layout c0,c1 = (row g, cols 2t..2t+1); c2,c3 = row g+8 ----
    #pragma unroll
    for (int im = 0; im < MA; im++) {
        #pragma unroll
        for (int in_ = 0; in_ < 4; in_++) {
            int col = bn + wn + in_ * 8 + t * 2;
            float2 bv = *(const float2*)(bias + col);
            int r0 = bm + wm + im * 16 + g;
            float2 v0 = { acc[im][in_][0] + bv.x, acc[im][in_][1] + bv.y };
            float2 v1 = { acc[im][in_][2] + bv.x, acc[im][in_][3] + bv.y };
            *(float2*)(C + (long)r0 * ldc + col)       = v0;
            *(float2*)(C + (long)(r0 + 8) * ldc + col) = v1;
        }
    }
}

// ================= RoPE =================
__device__ __forceinline__ void rope_pair(int pos, int j, float& x1, float& x2)
{
    const float LOG2_THETA = 13.287712379549449f;
    float e   = (float)(2 * j) * (1.0f / (float)RD_);
    float inv = exp2f(-e * LOG2_THETA);
    float ang = (float)pos * inv;
    float s, c;
    sincosf(ang, &s, &c);
    float a = x1, b = x2;
    x1 = a * c - b * s;
    x2 = b * c + a * s;
}

__global__ void rope_kr_kernel()
{
    int r = blockIdx.x, j = threadIdx.x;
    int pos = r & (T_ - 1);
    float* p = g_KR + (long)r * RD_;
    float x1 = p[j], x2 = p[j + 32];
    rope_pair(pos, j, x1, x2);
    p[j] = x1; p[j + 32] = x2;
}

__global__ void rope_q_kernel()
{
    int r = blockIdx.x, tid = threadIdx.x;
    int h = tid >> 5, j = tid & 31;
    int pos = r & (T_ - 1);
    float* p = g_Q + (long)r * D_ + h * HD_ + CD_;
    float x1 = p[j], x2 = p[j + 32];
    rope_pair(pos, j, x1, x2);
    p[j] = x1; p[j + 32] = x2;
}

// ================= fp32 flash attention (FFMA2 core, from R4) =================
#define FL_SMEM_FLOATS (2*128*68 + 64*128 + 64*65 + 3*64)
#define FL_SMEM_BYTES  (FL_SMEM_FLOATS * 4)

__global__ __launch_bounds__(256) void flash_kernel()
{
    extern __shared__ float sm[];
    float* sQt = sm;
    float* sKt = sQt + 128*68;
    float* sV  = sKt + 128*68;
    float* sP  = sV  + 64*128;
    float* sM  = sP  + 64*65;
    float* sL  = sM  + 64;
    float* sSc = sL  + 64;

    const int qt = 31 - blockIdx.x;
    const int pr = blockIdx.y;
    const int b  = pr >> 4, h = pr & 15;
    const int tid = threadIdx.x;
    const int tx = tid & 15, ty = tid >> 4;
    const int q0 = qt * 64;
    const int rowbase = b * T_;

    #pragma unroll 8
    for (int idx = tid; idx < 64*128; idx += 256) {
        int qi = idx >> 7, d = idx & 127;
        sQt[d*68 + qi] = g_Q[(long)(rowbase + q0 + qi) * D_ + h*HD_ + d];
    }
    if (tid < 64) { sM[tid] = -INFINITY; sL[tid] = 0.f; }

    ull accO2[4][4];
    #pragma unroll
    for (int i = 0; i < 4; i++)
        #pragma unroll
        for (int jp = 0; jp < 4; jp++) accO2[i][jp] = 0ull;

    const float sc_qk = 0.08838834764831845f;

    for (int kb = 0; kb <= qt; kb++) {
        const int k0 = kb * 64;
        __syncthreads();
        #pragma unroll 8
        for (int idx = tid; idx < 64*128; idx += 256) {
            int ki = idx >> 7, d = idx & 127;
            int r  = rowbase + k0 + ki;
            float kv = (d < CD_) ? g_KC[(long)r * (H_*CD_) + h*CD_ + d]
                                 : g_KR[(long)r * RD_ + (d - CD_)];
            sKt[d*68 + ki]  = kv;
            sV [ki*128 + d] = g_V[(long)r * D_ + h*HD_ + d];
        }
        __syncthreads();

        ull s2[4][2];
        #pragma unroll
        for (int i = 0; i < 4; i++) { s2[i][0] = 0ull; s2[i][1] = 0ull; }
        #pragma unroll 4
        for (int d = 0; d < 128; d++) {
            float4 a = *(const float4*)&sQt[d*68 + ty*4];
            ulonglong2 kp = *(const ulonglong2*)&sKt[d*68 + tx*4];
            ull a0 = splat2(a.x), a1 = splat2(a.y);
            ull a2 = splat2(a.z), a3 = splat2(a.w);
            s2[0][0] = ffma2(a0, kp.x, s2[0][0]); s2[0][1] = ffma2(a0, kp.y, s2[0][1]);
            s2[1][0] = ffma2(a1, kp.x, s2[1][0]); s2[1][1] = ffma2(a1, kp.y, s2[1][1]);
            s2[2][0] = ffma2(a2, kp.x, s2[2][0]); s2[2][1] = ffma2(a2, kp.y, s2[2][1]);
            s2[3][0] = ffma2(a3, kp.x, s2[3][0]); s2[3][1] = ffma2(a3, kp.y, s2[3][1]);
        }
        {
            const bool diag = (kb == qt);
            #pragma unroll
            for (int i = 0; i < 4; i++) {
                #pragma unroll
                for (int jp = 0; jp < 2; jp++) {
                    float2 sv = unpack2(s2[i][jp]);
                    int j0 = tx*4 + jp*2;
                    float v0 = sv.x * sc_qk;
                    float v1 = sv.y * sc_qk;
                    if (diag && (j0     > ty*4 + i)) v0 = -INFINITY;
                    if (diag && (j0 + 1 > ty*4 + i)) v1 = -INFINITY;
                    sP[(ty*4 + i)*65 + j0]     = v0;
                    sP[(ty*4 + i)*65 + j0 + 1] = v1;
                }
            }
        }
        __syncthreads();

        if (tid < 64) {
            float* row = sP + tid*65;
            float mold = sM[tid];
            float mx = mold;
            #pragma unroll 8
            for (int j = 0; j < 64; j++) mx = fmaxf(mx, row[j]);
            float scl = __expf(mold - mx);
            float sum = 0.f;
            #pragma unroll 8
            for (int j = 0; j < 64; j++) {
                float e = __expf(row[j] - mx);
                row[j] = e;
                sum += e;
            }
            sL[tid]  = sL[tid] * scl + sum;
            sM[tid]  = mx;
            sSc[tid] = scl;
        }
        __syncthreads();

        {
            ull f0 = splat2(sSc[ty*4+0]), f1 = splat2(sSc[ty*4+1]);
            ull f2 = splat2(sSc[ty*4+2]), f3 = splat2(sSc[ty*4+3]);
            #pragma unroll
            for (int jp = 0; jp < 4; jp++) {
                accO2[0][jp] = fmul2(accO2[0][jp], f0);
                accO2[1][jp] = fmul2(accO2[1][jp], f1);
                accO2[2][jp] = fmul2(accO2[2][jp], f2);
                accO2[3][jp] = fmul2(accO2[3][jp], f3);
            }
        }
        #pragma unroll 2
        for (int k = 0; k < 64; k++) {
            ull p0 = splat2(sP[(ty*4+0)*65 + k]);
            ull p1 = splat2(sP[(ty*4+1)*65 + k]);
            ull p2 = splat2(sP[(ty*4+2)*65 + k]);
            ull p3 = splat2(sP[(ty*4+3)*65 + k]);
            ulonglong2 v0 = *(const ulonglong2*)&sV[k*128 + tx*8];
            ulonglong2 v1 = *(const ulonglong2*)&sV[k*128 + tx*8 + 4];
            accO2[0][0] = ffma2(p0, v0.x, accO2[0][0]);
            accO2[0][1] = ffma2(p0, v0.y, accO2[0][1]);
            accO2[0][2] = ffma2(p0, v1.x, accO2[0][2]);
            accO2[0][3] = ffma2(p0, v1.y, accO2[0][3]);
            accO2[1][0] = ffma2(p1, v0.x, accO2[1][0]);
            accO2[1][1] = ffma2(p1, v0.y, accO2[1][1]);
            accO2[1][2] = ffma2(p1, v1.x, accO2[1][2]);
            accO2[1][3] = ffma2(p1, v1.y, accO2[1][3]);
            accO2[2][0] = ffma2(p2, v0.x, accO2[2][0]);
            accO2[2][1] = ffma2(p2, v0.y, accO2[2][1]);
            accO2[2][2] = ffma2(p2, v1.x, accO2[2][2]);
            accO2[2][3] = ffma2(p2, v1.y, accO2[2][3]);
            accO2[3][0] = ffma2(p3, v0.x, accO2[3][0]);
            accO2[3][1] = ffma2(p3, v0.y, accO2[3][1]);
            accO2[3][2] = ffma2(p3, v1.x, accO2[3][2]);
            accO2[3][3] = ffma2(p3, v1.y, accO2[3][3]);
        }
    }

    #pragma unroll
    for (int i = 0; i < 4; i++) {
        float inv = 1.f / sL[ty*4 + i];
        float* outp = g_O + (long)(rowbase + q0 + ty*4 + i) * D_ + h*HD_ + tx*8;
        #pragma unroll
        for (int jp = 0; jp < 4; jp++) {
            float2 c = unpack2(accO2[i][jp]);
            outp[jp*2]     = c.x * inv;
            outp[jp*2 + 1] = c.y * inv;
        }
    }
}

// ================= launcher =================
extern "C" void kernel_launch(void* const* d_in, const int* in_sizes, int n_in,
                              void* d_out, int out_size)
{
    const float* x   = (const float*)d_in[0];
    const float* Wq  = (const float*)d_in[1];
    const float* bq  = (const float*)d_in[2];
    const float* Wkv = (const float*)d_in[3];
    const float* bkv = (const float*)d_in[4];
    const float* Wkr = (const float*)d_in[5];
    const float* bkr = (const float*)d_in[6];
    const float* Wku = (const float*)d_in[7];
    const float* bku = (const float*)d_in[8];
    const float* Wvu = (const float*)d_in[9];
    const float* bvu = (const float*)d_in[10];
    const float* Wo  = (const float*)d_in[11];
    const float* bo  = (const float*)d_in[12];
    float* out = (float*)d_out;

    void *pQ, *pKV, *pKR, *pKC, *pV, *pO;
    cudaGetSymbolAddress(&pQ,  g_Q);
    cudaGetSymbolAddress(&pKV, g_KV);
    cudaGetSymbolAddress(&pKR, g_KR);
    cudaGetSymbolAddress(&pKC, g_KC);
    cudaGetSymbolAddress(&pV,  g_V);
    cudaGetSymbolAddress(&pO,  g_O);
    void *pxh, *pxl, *pWqh, *pWql, *pWkvh, *pWkvl, *pWkrh, *pWkrl;
    void *pWkuh, *pWkul, *pWvuh, *pWvul, *pWoh, *pWol, *pKVh, *pKVl, *pOh, *pOl;
    cudaGetSymbolAddress(&pxh,  g_xh);   cudaGetSymbolAddress(&pxl,  g_xl);
    cudaGetSymbolAddress(&pWqh, g_Wqh);  cudaGetSymbolAddress(&pWql, g_Wql);
    cudaGetSymbolAddress(&pWkvh,g_Wkvh); cudaGetSymbolAddress(&pWkvl,g_Wkvl);
    cudaGetSymbolAddress(&pWkrh,g_Wkrh); cudaGetSymbolAddress(&pWkrl,g_Wkrl);
    cudaGetSymbolAddress(&pWkuh,g_Wkuh); cudaGetSymbolAddress(&pWkul,g_Wkul);
    cudaGetSymbolAddress(&pWvuh,g_Wvuh); cudaGetSymbolAddress(&pWvul,g_Wvul);
    cudaGetSymbolAddress(&pWoh, g_Woh);  cudaGetSymbolAddress(&pWol, g_Wol);
    cudaGetSymbolAddress(&pKVh, g_KVh);  cudaGetSymbolAddress(&pKVl, g_KVl);
    cudaGetSymbolAddress(&pOh,  g_Oh);   cudaGetSymbolAddress(&pOl,  g_Ol);

    cudaFuncSetAttribute(flash_kernel,
                         cudaFuncAttributeMaxDynamicSharedMemorySize, FL_SMEM_BYTES);

    auto SPL = [](const float* s, void* h, void* l, int n) {
        split_f32_bf16<<<n/1024, 256>>>(s, (__nv_bfloat16*)h, (__nv_bfloat16*)l, n);
    };

    // input + weight splits
    SPL(x,   pxh,   pxl,   M_*D_);
    SPL(Wq,  pWqh,  pWql,  D_*D_);
    SPL(Wkv, pWkvh, pWkvl, 2*LAT_*D_);
    SPL(Wkr, pWkrh, pWkrl, RD_*D_);
    SPL(Wku, pWkuh, pWkul, H_*CD_*LAT_);
    SPL(Wvu, pWvuh, pWvul, D_*LAT_);
    SPL(Wo,  pWoh,  pWol,  D_*D_);

    // Q = x Wq^T + bq
    gemm_hmma_3p<128><<<dim3(16, 32), 256>>>(
        (__nv_bfloat16*)pxh, (__nv_bfloat16*)pxl, D_, 0,
        (__nv_bfloat16*)pWqh, (__nv_bfloat16*)pWql, bq, (float*)pQ, D_, D_);
    // KV = x Wkv^T + bkv
    gemm_hmma_3p<128><<<dim3(8, 32), 256>>>(
        (__nv_bfloat16*)pxh, (__nv_bfloat16*)pxl, D_, 0,
        (__nv_bfloat16*)pWkvh, (__nv_bfloat16*)pWkvl, bkv, (float*)pKV, 2*LAT_, D_);
    // KR = x Wkr^T + bkr
    gemm_hmma_3p<64><<<dim3(1, 32), 256>>>(
        (__nv_bfloat16*)pxh, (__nv_bfloat16*)pxl, D_, 0,
        (__nv_bfloat16*)pWkrh, (__nv_bfloat16*)pWkrl, bkr, (float*)pKR, RD_, D_);
    rope_kr_kernel<<<M_, 32>>>();

    // split KV for up-projections
    SPL((const float*)pKV, pKVh, pKVl, M_*2*LAT_);

    // KC = k_lat Wku^T + bku
    gemm_hmma_3p<128><<<dim3(8, 32), 256>>>(
        (__nv_bfloat16*)pKVh, (__nv_bfloat16*)pKVl, 2*LAT_, 0,
        (__nv_bfloat16*)pWkuh, (__nv_bfloat16*)pWkul, bku, (float*)pKC, H_*CD_, LAT_);
    // V = v_lat Wvu^T + bvu
    gemm_hmma_3p<128><<<dim3(16, 32), 256>>>(
        (__nv_bfloat16*)pKVh, (__nv_bfloat16*)pKVl, 2*LAT_, LAT_,
        (__nv_bfloat16*)pWvuh, (__nv_bfloat16*)pWvul, bvu, (float*)pV, D_, LAT_);

    rope_q_kernel<<<M_, 512>>>();
    flash_kernel<<<dim3(32, 32), 256, FL_SMEM_BYTES>>>();

    // split O, then out = O Wo^T + bo
    SPL((const float*)pO, pOh, pOl, M_*D_);
    gemm_hmma_3p<128><<<dim3(16, 32), 256>>>(
        (__nv_bfloat16*)pOh, (__nv_bfloat16*)pOl, D_, 0,
        (__nv_bfloat16*)pWoh, (__nv_bfloat16*)pWol, bo, out, D_, D_);
}